// round 17
// baseline (speedup 1.0000x reference)
#include <cuda_runtime.h>
#include <cuda_fp16.h>
#include <math.h>

#define BG   64
#define NPG  2048
#define EPG  32768
#define NTOT (BG * NPG)         // 131072
#define EDG  (BG * EPG)         // 2097152
#define K1   1639
#define NT1  (BG * K1)          // 104896 (divisible by 64)
#define K2   1312
#define NT2  (BG * K2)          // 83968
#define DIM  64
#define NCLS 6
#define CAP  64                 // fixed CSR bucket capacity (P(deg>=64) ~ 1e-20)
#define FULLMASK 0xFFFFFFFFu

typedef unsigned long long ull;

// ---------------- scratch ----------------------------------------------------
__device__ __half g_xw[NTOT * DIM];      // (A@W) rows fp16; scaled by rdeg in scale_kernel
__device__ float  g_h[NTOT * DIM];       // conv output (relu'd), fp32
__device__ float  g_score[NTOT];
__device__ float  g_rdeg[NTOT];          // rsqrt(deg incl self-loop)
__device__ int    g_cnt[NTOT];           // in-degree (excl self-loop)
__device__ int    g_elist[NTOT * CAP];   // fixed-stride CSR: src per dst-slot
__device__ int    g_perm[NT1];
__device__ float  g_vals[NT1];
__device__ int    g_newid[NTOT];
__device__ float  g_x1[BG * 2 * DIM];
__device__ float  g_x2[BG * 2 * DIM];

// ---------------- packed f32x2 add (PTX-only; ptxas never auto-emits) --------
__device__ __forceinline__ void add2(ull& d, ull a) {
    asm("add.rn.f32x2 %0, %0, %1;" : "+l"(d) : "l"(a));
}

// pack two floats to half2 bits (helper for scale_kernel)
__device__ __forceinline__ unsigned f2_to_h2bits(float2 f) {
    __half2 h = __floats2half2_rn(f.x, f.y);
    return *(unsigned*)&h;
}

// fused count + place, 4 edges/thread via int4 (stage 1: all edges valid)
__global__ void place1_kernel(const int4* __restrict__ src4, const int4* __restrict__ dst4,
                              int* __restrict__ cnt, int* __restrict__ elist, int nedge4) {
    int t = blockIdx.x * blockDim.x + threadIdx.x;
    if (t >= nedge4) return;
    int4 s = src4[t];
    int4 d = dst4[t];
    int slot;
    slot = atomicAdd(&cnt[d.x], 1); elist[d.x * CAP + slot] = s.x;
    slot = atomicAdd(&cnt[d.y], 1); elist[d.y * CAP + slot] = s.y;
    slot = atomicAdd(&cnt[d.z], 1); elist[d.z * CAP + slot] = s.z;
    slot = atomicAdd(&cnt[d.w], 1); elist[d.w * CAP + slot] = s.w;
}

// fused remap + count + place, 4 edges/thread (stage 2)
__global__ void place2_kernel(const int4* __restrict__ src4, const int4* __restrict__ dst4,
                              const int* __restrict__ newid,
                              int* __restrict__ cnt, int* __restrict__ elist, int nedge4) {
    int t = blockIdx.x * blockDim.x + threadIdx.x;
    if (t >= nedge4) return;
    int4 s = src4[t];
    int4 d = dst4[t];
    int s2, d2, slot;
    s2 = newid[s.x]; d2 = newid[d.x];
    if (s2 >= 0 && d2 >= 0) { slot = atomicAdd(&cnt[d2], 1); elist[d2 * CAP + slot] = s2; }
    s2 = newid[s.y]; d2 = newid[d.y];
    if (s2 >= 0 && d2 >= 0) { slot = atomicAdd(&cnt[d2], 1); elist[d2 * CAP + slot] = s2; }
    s2 = newid[s.z]; d2 = newid[d.z];
    if (s2 >= 0 && d2 >= 0) { slot = atomicAdd(&cnt[d2], 1); elist[d2 * CAP + slot] = s2; }
    s2 = newid[s.w]; d2 = newid[d.w];
    if (s2 >= 0 && d2 >= 0) { slot = atomicAdd(&cnt[d2], 1); elist[d2 * CAP + slot] = s2; }
}

// ---------------- GEMM (UNSCALED): xw16[i] = fp16( (gather(A) @ W)[i] ) ------
// 64-row tile; thread = 4 rows x 4 cols. No cnt/rdeg dependency -> runs
// concurrently with the CSR build on another stream.
// If perm != nullptr, row i of A is A[perm[i]] * vals[i] (fused TopK gather+gate).
__global__ __launch_bounds__(256, 4) void matmul64_kernel(
    const float* __restrict__ A, const float* __restrict__ W,
    const int* __restrict__ perm, const float* __restrict__ vals,
    __half* __restrict__ C, int nrows) {
    __shared__ float Ws[16][64][4];   // [k4][col][k-in-group]
    __shared__ float As[64][64];
    int tid = threadIdx.x;
    for (int i = tid; i < 4096; i += 256) {
        int k = i >> 6, j = i & 63;
        Ws[k >> 2][j][k & 3] = W[i];
    }
    int row0 = blockIdx.x * 64;
    {
        float4* s4 = (float4*)&As[0][0];
        for (int i = tid; i < 1024; i += 256) {
            int grow = row0 + (i >> 4);       // grow < nrows (nrows % 64 == 0)
            int arow = perm ? perm[grow] : grow;
            float sc = perm ? vals[grow] : 1.0f;
            float4 v = ((const float4*)(A + (size_t)arow * 64))[i & 15];
            v.x *= sc; v.y *= sc; v.z *= sc; v.w *= sc;
            s4[i] = v;
        }
    }
    __syncthreads();
    int tx = tid & 15;
    int ty = tid >> 4;
    float acc[4][4] = {};
#pragma unroll
    for (int k4 = 0; k4 < 16; k4++) {
        float4 w[4];
#pragma unroll
        for (int c = 0; c < 4; c++)
            w[c] = *(const float4*)&Ws[k4][tx + 16 * c][0];
#pragma unroll
        for (int r = 0; r < 4; r++) {
            float4 a = *(const float4*)&As[ty * 4 + r][k4 * 4];
#pragma unroll
            for (int c = 0; c < 4; c++)
                acc[r][c] += a.x * w[c].x + a.y * w[c].y + a.z * w[c].z + a.w * w[c].w;
        }
    }
#pragma unroll
    for (int r = 0; r < 4; r++) {
        int row = row0 + ty * 4 + r;
#pragma unroll
        for (int c = 0; c < 4; c++)
            C[(size_t)row * 64 + tx + 16 * c] = __float2half_rn(acc[r][c]);
    }
}

// ---------------- scale pass: rdeg[i]=rsqrt(cnt+1); xw16 row *= rdeg ---------
// 4 threads/row, 2 uint4 each (doubled ILP vs R16's 8 threads/row).
__global__ void scale_kernel(__half* __restrict__ xwh, const int* __restrict__ cnt,
                             float* __restrict__ rdeg, int n) {
    int t = blockIdx.x * blockDim.x + threadIdx.x;  // n*4 threads, 16 cols each
    int node = t >> 2, q = t & 3;
    if (node >= n) return;
    float rr = rsqrtf((float)(cnt[node] + 1));
    if (q == 0) rdeg[node] = rr;
    uint4* p = (uint4*)(xwh + (size_t)node * 64 + q * 16);
    uint4 v0 = p[0];
    uint4 v1 = p[1];
    unsigned* a = (unsigned*)&v0;
    unsigned* b = (unsigned*)&v1;
#pragma unroll
    for (int i = 0; i < 4; i++) {
        float2 f = __half22float2(*(const __half2*)&a[i]);
        f.x *= rr; f.y *= rr;
        a[i] = f2_to_h2bits(f);
        float2 g = __half22float2(*(const __half2*)&b[i]);
        g.x *= rr; g.y *= rr;
        b[i] = f2_to_h2bits(g);
    }
    p[0] = v0;
    p[1] = v1;
}

// ---------------- fused CSR-gather conv + epilogue + score -------------------
__global__ __launch_bounds__(256) void conv_kernel(
    const int* __restrict__ cnt, const int* __restrict__ elist,
    const float* __restrict__ rdeg, const __half* __restrict__ xwh,
    const float* __restrict__ bias, const float* __restrict__ p,
    float* __restrict__ h, float* __restrict__ score, int n) {
    int warp = (blockIdx.x * blockDim.x + threadIdx.x) >> 5;
    int lane = threadIdx.x & 31;
    if (warp >= n) return;
    int li   = lane & 15;
    int half = lane >> 4;
    float rd = rdeg[warp];
    int m = cnt[warp];
    const int* el = elist + (size_t)warp * CAP;
    ull a01 = 0, a23 = 0;
    int e = half;
#pragma unroll 2
    for (; e + 2 < m; e += 4) {
        int s0 = el[e], s1 = el[e + 2];
        uint2 v0 = *(const uint2*)((const char*)xwh + ((size_t)s0 << 7) + (li << 3));
        uint2 v1 = *(const uint2*)((const char*)xwh + ((size_t)s1 << 7) + (li << 3));
        __half2 pA = __hadd2(*(const __half2*)&v0.x, *(const __half2*)&v1.x);
        __half2 pB = __hadd2(*(const __half2*)&v0.y, *(const __half2*)&v1.y);
        float2 f0 = __half22float2(pA);
        float2 f1 = __half22float2(pB);
        add2(a01, *(const ull*)&f0);
        add2(a23, *(const ull*)&f1);
    }
    if (e < m) {
        int s = el[e];
        uint2 hv = *(const uint2*)((const char*)xwh + ((size_t)s << 7) + (li << 3));
        float2 f0 = __half22float2(*(const __half2*)&hv.x);
        float2 f1 = __half22float2(*(const __half2*)&hv.y);
        add2(a01, *(const ull*)&f0);
        add2(a23, *(const ull*)&f1);
    }
    float2 f01 = *(float2*)&a01;
    float2 f23 = *(float2*)&a23;
    float4 acc = make_float4(f01.x, f01.y, f23.x, f23.y);
    acc.x += __shfl_xor_sync(FULLMASK, acc.x, 16);
    acc.y += __shfl_xor_sync(FULLMASK, acc.y, 16);
    acc.z += __shfl_xor_sync(FULLMASK, acc.z, 16);
    acc.w += __shfl_xor_sync(FULLMASK, acc.w, 16);
    uint2 sv = *(const uint2*)((const char*)xwh + ((size_t)warp << 7) + (li << 3));
    float2 s0 = __half22float2(*(const __half2*)&sv.x);
    float2 s1 = __half22float2(*(const __half2*)&sv.y);
    float4 b4 = ((const float4*)bias)[li];
    acc.x = fmaxf((acc.x + s0.x) * rd + b4.x, 0.f);
    acc.y = fmaxf((acc.y + s0.y) * rd + b4.y, 0.f);
    acc.z = fmaxf((acc.z + s1.x) * rd + b4.z, 0.f);
    acc.w = fmaxf((acc.w + s1.y) * rd + b4.w, 0.f);
    if (half == 0) ((float4*)h)[(size_t)warp * 16 + li] = acc;
    float4 p4 = ((const float4*)p)[li];
    float dot = acc.x * p4.x + acc.y * p4.y + acc.z * p4.z + acc.w * p4.w;
    float pp  = p4.x * p4.x + p4.y * p4.y + p4.z * p4.z + p4.w * p4.w;
#pragma unroll
    for (int o = 16; o; o >>= 1) {
        dot += __shfl_down_sync(FULLMASK, dot, o);
        pp  += __shfl_down_sync(FULLMASK, pp, o);
    }
    if (lane == 0) score[warp] = tanhf(dot * rsqrtf(pp) * 0.7071067811865476f);
}

// ---------------- per-graph top-k via EXACT RADIX-SELECT + fused readout -----
// Optionally also runs the MLP head (topk2: headOut != nullptr), using x1 from
// global (written by topk1) and the just-computed x2 readout in smem.
__global__ __launch_bounds__(1024) void topk_kernel(
    const float* __restrict__ score, const float* __restrict__ h,
    int n_per, int k,
    int* __restrict__ perm, float* __restrict__ vals, int* __restrict__ newid,
    int* __restrict__ cnt_zero, float* __restrict__ out,
    const float* __restrict__ x1, const float* __restrict__ l1w,
    const float* __restrict__ l1b, const float* __restrict__ l2w,
    const float* __restrict__ l2b, float* __restrict__ headOut) {
    __shared__ unsigned keys[2048];
    __shared__ int sel[2048];
    __shared__ int hist[256];
    __shared__ int sbuf[1024];
    __shared__ float smx[1024], ssm[1024];
    __shared__ int s_thr, s_kRem, s_ctr;
    __shared__ float hv[128];
    __shared__ float h1[64];
    int b = blockIdx.x;
    int tid = threadIdx.x;
    const float* sc = score + (size_t)b * n_per;
    for (int i = tid; i < 2048; i += 1024) {
        unsigned u = 0;
        if (i < n_per) {
            u = __float_as_uint(sc[i]);
            u = (u & 0x80000000u) ? ~u : (u | 0x80000000u);
        }
        keys[i] = u;
    }
    unsigned pfx = 0, pfxMask = 0;
    int kRem = k;
    for (int shift = 24; shift >= 0; shift -= 8) {
        if (tid < 256) hist[tid] = 0;
        __syncthreads();
        for (int i = tid; i < 2048; i += 1024) {
            unsigned u = keys[i];
            if ((u & pfxMask) == pfx) atomicAdd(&hist[(u >> shift) & 255u], 1);
        }
        __syncthreads();
        if (tid < 256) sbuf[tid] = hist[255 - tid];
        __syncthreads();
        for (int off = 1; off < 256; off <<= 1) {
            int t = (tid < 256 && tid >= off) ? sbuf[tid - off] : 0;
            __syncthreads();
            if (tid < 256) sbuf[tid] += t;
            __syncthreads();
        }
        if (tid < 256) {
            int x = 255 - tid;
            int sInc = sbuf[tid];
            int sExc = sInc - hist[x];
            if (sExc < kRem && kRem <= sInc) { s_thr = x; s_kRem = kRem - sExc; }
        }
        __syncthreads();
        pfx |= ((unsigned)s_thr) << shift;
        pfxMask |= 255u << shift;
        kRem = s_kRem;
        __syncthreads();
    }
    unsigned T = pfx;
    int base = k - kRem;
    if (tid == 0) s_ctr = 0;
    __syncthreads();
    for (int i = tid; i < n_per; i += 1024) {
        if (keys[i] > T) { int pos = atomicAdd(&s_ctr, 1); sel[pos] = i; }
    }
    __syncthreads();
    int i0 = 2 * tid, i1 = 2 * tid + 1;
    int e0 = (i0 < n_per) && (keys[i0] == T);
    int e1 = (i1 < n_per) && (keys[i1] == T);
    sbuf[tid] = e0 + e1;
    __syncthreads();
    for (int off = 1; off < 1024; off <<= 1) {
        int t = (tid >= off) ? sbuf[tid - off] : 0;
        __syncthreads();
        sbuf[tid] += t;
        __syncthreads();
    }
    int pre = sbuf[tid] - (e0 + e1);
    if (e0 && pre < kRem)       sel[base + pre]       = i0;
    if (e1 && pre + e0 < kRem)  sel[base + pre + e0]  = i1;
    __syncthreads();
    for (int r = tid; r < k; r += 1024) {
        int idx = sel[r];
        if (perm)     perm[b * k + r] = b * n_per + idx;
        if (vals)     vals[b * k + r] = sc[idx];
        if (newid)    newid[b * n_per + idx] = b * k + r;
        if (cnt_zero) cnt_zero[b * k + r] = 0;
    }
    int j  = tid & 63;
    int rg = tid >> 6;
    float mx = -INFINITY, sum = 0.f;
    for (int r = rg; r < k; r += 16) {
        int idx = sel[r];
        float val = sc[idx];
        float v = h[((size_t)b * n_per + idx) * 64 + j] * val;
        mx = fmaxf(mx, v);
        sum += v;
    }
    smx[tid] = mx;
    ssm[tid] = sum;
    __syncthreads();
    for (int s = 8; s >= 1; s >>= 1) {
        if (rg < s) {
            smx[rg * 64 + j] = fmaxf(smx[rg * 64 + j], smx[(rg + s) * 64 + j]);
            ssm[rg * 64 + j] += ssm[(rg + s) * 64 + j];
        }
        __syncthreads();
    }
    if (rg == 0) {
        float xmax = smx[j];
        float xmean = ssm[j] / (float)k;
        if (out) {
            out[b * 128 + j]      = xmax;
            out[b * 128 + 64 + j] = xmean;
        }
        if (headOut) {
            hv[j]      = x1[b * 128 + j]      + xmax;
            hv[j + 64] = x1[b * 128 + 64 + j] + xmean;
        }
    }
    if (!headOut) return;
    // ---- fused MLP head for graph b (threads 0..63) ----
    __syncthreads();
    if (tid < 64) {
        float acc = l1b[tid];
#pragma unroll 8
        for (int kk = 0; kk < 128; kk++) acc += hv[kk] * l1w[kk * 64 + tid];
        h1[tid] = fmaxf(acc, 0.f);
    }
    __syncthreads();
    if (tid < NCLS) {
        float o = l2b[tid];
#pragma unroll 8
        for (int kk = 0; kk < 64; kk++) o += h1[kk] * l2w[kk * NCLS + tid];
        headOut[b * NCLS + tid] = o;
    }
}

// ---------------- host orchestration (two-stream fork/join) ------------------
extern "C" void kernel_launch(void* const* d_in, const int* in_sizes, int n_in,
                              void* d_out, int out_size) {
    const float* x   = (const float*)d_in[0];
    const int* ei    = (const int*)d_in[1];
    const float* W1  = (const float*)d_in[3];
    const float* b1  = (const float*)d_in[4];
    const float* p1  = (const float*)d_in[5];
    const float* W2  = (const float*)d_in[6];
    const float* b2  = (const float*)d_in[7];
    const float* p2  = (const float*)d_in[8];
    const float* l1w = (const float*)d_in[9];
    const float* l1b = (const float*)d_in[10];
    const float* l2w = (const float*)d_in[11];
    const float* l2b = (const float*)d_in[12];
    float* out = (float*)d_out;

    const int4* src4 = (const int4*)ei;
    const int4* dst4 = (const int4*)(ei + EDG);

    float *h, *score, *rdeg, *vals, *x1, *x2;
    __half* xwh;
    int *cnt, *elist, *perm, *newid;
    cudaGetSymbolAddress((void**)&xwh,    g_xw);
    cudaGetSymbolAddress((void**)&h,      g_h);
    cudaGetSymbolAddress((void**)&score,  g_score);
    cudaGetSymbolAddress((void**)&rdeg,   g_rdeg);
    cudaGetSymbolAddress((void**)&cnt,    g_cnt);
    cudaGetSymbolAddress((void**)&elist,  g_elist);
    cudaGetSymbolAddress((void**)&perm,   g_perm);
    cudaGetSymbolAddress((void**)&newid,  g_newid);
    cudaGetSymbolAddress((void**)&vals,   g_vals);
    cudaGetSymbolAddress((void**)&x1,     g_x1);
    cudaGetSymbolAddress((void**)&x2,     g_x2);

    static cudaStream_t sB = nullptr;
    static cudaEvent_t evRoot, evM1, evT1, evM2;
    if (!sB) {
        cudaStreamCreateWithFlags(&sB, cudaStreamNonBlocking);
        cudaEventCreateWithFlags(&evRoot, cudaEventDisableTiming);
        cudaEventCreateWithFlags(&evM1,   cudaEventDisableTiming);
        cudaEventCreateWithFlags(&evT1,   cudaEventDisableTiming);
        cudaEventCreateWithFlags(&evM2,   cudaEventDisableTiming);
    }
    cudaStream_t sA = 0;

    const int TB = 256;
    const int E4 = EDG / 4;
    const int EB4 = (E4 + TB - 1) / TB;

    // ===================== Stage 1 =====================
    cudaEventRecord(evRoot, sA);
    cudaStreamWaitEvent(sB, evRoot, 0);
    matmul64_kernel<<<NTOT / 64, TB, 0, sB>>>(x, W1, nullptr, nullptr, xwh, NTOT);
    cudaEventRecord(evM1, sB);

    cudaMemsetAsync(cnt, 0, NTOT * sizeof(int), sA);
    cudaMemsetAsync(newid, 0xFF, NTOT * sizeof(int), sA);   // -1 for int
    place1_kernel<<<EB4, TB, 0, sA>>>(src4, dst4, cnt, elist, E4);

    cudaStreamWaitEvent(sA, evM1, 0);
    scale_kernel<<<(NTOT * 4 + TB - 1) / TB, TB, 0, sA>>>(xwh, cnt, rdeg, NTOT);
    conv_kernel<<<(NTOT * 32 + TB - 1) / TB, TB, 0, sA>>>(cnt, elist, rdeg, xwh, b1, p1, h, score, NTOT);
    topk_kernel<<<BG, 1024, 0, sA>>>(score, h, NPG, K1, perm, vals, newid, cnt, x1,
                                     nullptr, nullptr, nullptr, nullptr, nullptr, nullptr);

    // ===================== Stage 2 =====================
    cudaEventRecord(evT1, sA);
    cudaStreamWaitEvent(sB, evT1, 0);
    matmul64_kernel<<<NT1 / 64, TB, 0, sB>>>(h, W2, perm, vals, xwh, NT1);
    cudaEventRecord(evM2, sB);

    place2_kernel<<<EB4, TB, 0, sA>>>(src4, dst4, newid, cnt, elist, E4);

    cudaStreamWaitEvent(sA, evM2, 0);
    scale_kernel<<<(NT1 * 4 + TB - 1) / TB, TB, 0, sA>>>(xwh, cnt, rdeg, NT1);
    conv_kernel<<<(NT1 * 32 + TB - 1) / TB, TB, 0, sA>>>(cnt, elist, rdeg, xwh, b2, p2, h, score, NT1);
    // topk2 with fused readout + MLP head (x2 kept in smem; x1 read from global)
    topk_kernel<<<BG, 1024, 0, sA>>>(score, h, K1, K2,
                                     nullptr, nullptr, nullptr, nullptr, x2,
                                     x1, l1w, l1b, l2w, l2b, out);
}